// round 1
// baseline (speedup 1.0000x reference)
#include <cuda_runtime.h>
#include <cuda_bf16.h>
#include <cstdint>

#define BB 4
#define TE 512
#define TD 256
#define HE 128
#define HD 256

// ---- scratch (device globals; no allocation allowed) ----
__device__ float g_Ws[BB * TE * HE];   // enc @ W_a   [B,TE,HE]  (1 MB)
__device__ float g_Uh[BB * TD * HE];   // dec @ U_a   [B,TD,HE]  (0.5 MB)

__device__ __forceinline__ float fast_tanh(float x) {
    float y;
    asm("tanh.approx.f32 %0, %1;" : "=f"(y) : "f"(x));
    return y;
}

// ---------------- Kernel A: Uh = dec @ U  ----------------
// grid: B*TD/TTU blocks, 128 threads. Each block: TTU decoder rows.
#define TTU 8
__global__ void uh_kernel(const float* __restrict__ dec, const float* __restrict__ U) {
    __shared__ float sdec[TTU * HD];             // 8 KB
    int blk = blockIdx.x;
    int b  = blk / (TD / TTU);
    int t0 = (blk % (TD / TTU)) * TTU;
    int tid = threadIdx.x;                       // 0..127 -> output feature f

    const float* drow = dec + ((size_t)b * TD + t0) * HD;
    for (int i = tid; i < TTU * HD; i += 128) sdec[i] = drow[i];
    __syncthreads();

    float acc[TTU];
#pragma unroll
    for (int tt = 0; tt < TTU; tt++) acc[tt] = 0.f;

    for (int d = 0; d < HD; d++) {
        float u = U[d * HE + tid];               // coalesced across threads
#pragma unroll
        for (int tt = 0; tt < TTU; tt++) acc[tt] = fmaf(sdec[tt * HD + d], u, acc[tt]);
    }
#pragma unroll
    for (int tt = 0; tt < TTU; tt++)
        g_Uh[((size_t)(b * TD + t0 + tt)) * HE + tid] = acc[tt];
}

// ---------------- Kernel B: Ws = enc @ W  ----------------
#define TTW 16
__global__ void ws_kernel(const float* __restrict__ enc, const float* __restrict__ W) {
    __shared__ float senc[TTW * HE];             // 8 KB
    int blk = blockIdx.x;
    int b  = blk / (TE / TTW);
    int s0 = (blk % (TE / TTW)) * TTW;
    int tid = threadIdx.x;                       // 0..127

    const float* erow = enc + ((size_t)b * TE + s0) * HE;
    for (int i = tid; i < TTW * HE; i += 128) senc[i] = erow[i];
    __syncthreads();

    float acc[TTW];
#pragma unroll
    for (int ss = 0; ss < TTW; ss++) acc[ss] = 0.f;

    for (int k = 0; k < HE; k++) {
        float w = W[k * HE + tid];
#pragma unroll
        for (int ss = 0; ss < TTW; ss++) acc[ss] = fmaf(senc[ss * HE + k], w, acc[ss]);
    }
#pragma unroll
    for (int ss = 0; ss < TTW; ss++)
        g_Ws[((size_t)(b * TE + s0 + ss)) * HE + tid] = acc[ss];
}

// ------------- Kernel C: fused score/softmax/context -------------
// One CTA per (b, tile of TT decoder steps). 256 threads = 8 warps.
#define TT 4
__global__ __launch_bounds__(256) void score_ctx_kernel(
    const float* __restrict__ enc,
    const float* __restrict__ Va,
    float* __restrict__ c_out,   // [B,TD,HE]
    float* __restrict__ e_out)   // [B,TD,TE]
{
    __shared__ float s_uh[TT * HE];              // 2 KB
    __shared__ float s_scores[TT * TE];          // 8 KB
    __shared__ float s_ctx[TT * HE];             // 2 KB

    int blk = blockIdx.x;
    int b  = blk / (TD / TT);
    int t0 = (blk % (TD / TT)) * TT;
    int tid  = threadIdx.x;
    int warp = tid >> 5;
    int lane = tid & 31;

    // load Uh tile for the TT decoder steps
    for (int i = tid; i < TT * HE; i += 256)
        s_uh[i] = g_Uh[((size_t)(b * TD + t0)) * HE + i];
    __syncthreads();

    // registers: V and Uh as float4 slices (lane covers f = 4*lane..4*lane+3)
    float4 v4 = reinterpret_cast<const float4*>(Va)[lane];
    float4 uh4[TT];
#pragma unroll
    for (int tt = 0; tt < TT; tt++)
        uh4[tt] = reinterpret_cast<const float4*>(s_uh + tt * HE)[lane];

    // ---- Phase 1: scores. warp w handles s = w, w+8, ... (64 rows/warp)
    const float4* Ws4 = reinterpret_cast<const float4*>(g_Ws + (size_t)b * TE * HE);
    for (int s = warp; s < TE; s += 8) {
        float4 w4 = Ws4[s * (HE / 4) + lane];    // coalesced 512B/warp
#pragma unroll
        for (int tt = 0; tt < TT; tt++) {
            float p = fast_tanh(w4.x + uh4[tt].x) * v4.x
                    + fast_tanh(w4.y + uh4[tt].y) * v4.y
                    + fast_tanh(w4.z + uh4[tt].z) * v4.z
                    + fast_tanh(w4.w + uh4[tt].w) * v4.w;
#pragma unroll
            for (int o = 16; o > 0; o >>= 1)
                p += __shfl_xor_sync(0xFFFFFFFFu, p, o);
            if (lane == 0) s_scores[tt * TE + s] = p;
        }
    }
    __syncthreads();

    // ---- Phase 2: softmax per decoder step (warps 0..TT-1)
    if (warp < TT) {
        int tt = warp;
        float* sc = s_scores + tt * TE;
        float m = -1e30f;
        for (int s = lane; s < TE; s += 32) m = fmaxf(m, sc[s]);
#pragma unroll
        for (int o = 16; o > 0; o >>= 1)
            m = fmaxf(m, __shfl_xor_sync(0xFFFFFFFFu, m, o));
        float sum = 0.f;
        for (int s = lane; s < TE; s += 32) {
            float ex = __expf(sc[s] - m);
            sc[s] = ex;
            sum += ex;
        }
#pragma unroll
        for (int o = 16; o > 0; o >>= 1)
            sum += __shfl_xor_sync(0xFFFFFFFFu, sum, o);
        float inv = 1.0f / sum;
        float* eo = e_out + ((size_t)(b * TD + t0 + tt)) * TE;
        for (int s = lane; s < TE; s += 32) {
            float w = sc[s] * inv;
            sc[s] = w;
            eo[s] = w;
        }
    }
    __syncthreads();

    // ---- Phase 3: context c[tt, e'] = sum_s w[tt,s] * enc[b,s,e']
    // two thread-groups split the s range; combine via smem.
    int g  = tid >> 7;          // 0 or 1
    int ee = tid & 127;         // output feature
    const float* encb = enc + (size_t)b * TE * HE;
    float a0 = 0.f, a1 = 0.f, a2 = 0.f, a3 = 0.f;
    int sbeg = g * (TE / 2), send = sbeg + (TE / 2);
    for (int s = sbeg; s < send; s++) {
        float x = encb[(size_t)s * HE + ee];     // coalesced
        a0 = fmaf(s_scores[0 * TE + s], x, a0);
        a1 = fmaf(s_scores[1 * TE + s], x, a1);
        a2 = fmaf(s_scores[2 * TE + s], x, a2);
        a3 = fmaf(s_scores[3 * TE + s], x, a3);
    }
    if (g == 1) {
        s_ctx[0 * HE + ee] = a0;
        s_ctx[1 * HE + ee] = a1;
        s_ctx[2 * HE + ee] = a2;
        s_ctx[3 * HE + ee] = a3;
    }
    __syncthreads();
    if (g == 0) {
        a0 += s_ctx[0 * HE + ee];
        a1 += s_ctx[1 * HE + ee];
        a2 += s_ctx[2 * HE + ee];
        a3 += s_ctx[3 * HE + ee];
        c_out[((size_t)(b * TD + t0 + 0)) * HE + ee] = a0;
        c_out[((size_t)(b * TD + t0 + 1)) * HE + ee] = a1;
        c_out[((size_t)(b * TD + t0 + 2)) * HE + ee] = a2;
        c_out[((size_t)(b * TD + t0 + 3)) * HE + ee] = a3;
    }
}

extern "C" void kernel_launch(void* const* d_in, const int* in_sizes, int n_in,
                              void* d_out, int out_size) {
    const float* enc = (const float*)d_in[0];   // [B,TE,HE]
    const float* dec = (const float*)d_in[1];   // [B,TD,HD]
    const float* Wa  = (const float*)d_in[2];   // [HE,HE]
    const float* Ua  = (const float*)d_in[3];   // [HD,HE]
    const float* Va  = (const float*)d_in[4];   // [HE,1]

    float* out   = (float*)d_out;
    float* c_out = out;                          // [B,TD,HE] = 131072
    float* e_out = out + (size_t)BB * TD * HE;   // [B,TD,TE] = 524288

    uh_kernel<<<BB * TD / TTU, 128>>>(dec, Ua);
    ws_kernel<<<BB * TE / TTW, 128>>>(enc, Wa);
    score_ctx_kernel<<<BB * (TD / TT), 256>>>(enc, Va, c_out, e_out);
}

// round 2
// speedup vs baseline: 1.6701x; 1.6701x over previous
#include <cuda_runtime.h>
#include <cuda_bf16.h>
#include <cstdint>

#define BB 4
#define TE 512
#define TD 256
#define HE 128
#define HD 256

// ---- scratch (device globals; no allocation allowed) ----
__device__ float g_Ws[BB * TE * HE];   // enc @ W_a   [B,TE,HE]  (1 MB)
__device__ float g_Uh[BB * TD * HE];   // dec @ U_a   [B,TD,HE]  (0.5 MB)

__device__ __forceinline__ float fast_tanh(float x) {
    float y;
    asm("tanh.approx.f32 %0, %1;" : "=f"(y) : "f"(x));
    return y;
}

// ================= Prep kernel: Uh = dec@U  and  Ws = enc@W =================
// Blocks [0,256):   uh, 4 decoder rows per block
// Blocks [256,512): ws, 8 encoder rows per block
__global__ __launch_bounds__(128) void prep_kernel(
    const float* __restrict__ dec, const float* __restrict__ U,
    const float* __restrict__ enc, const float* __restrict__ W)
{
    __shared__ float sbuf[1024];                 // 4 KB, used by both halves
    int tid = threadIdx.x;

    if (blockIdx.x < 256) {
        // ---- Uh: rows = B*TD, 4 per block ----
        int blk = blockIdx.x;
        int b  = blk >> 6;
        int t0 = (blk & 63) * 4;
        const float4* drow = reinterpret_cast<const float4*>(dec + ((size_t)b * TD + t0) * HD);
        float4* sb4 = reinterpret_cast<float4*>(sbuf);
#pragma unroll
        for (int i = 0; i < 2; i++) sb4[tid + 128 * i] = drow[tid + 128 * i];
        __syncthreads();

        float a0 = 0.f, a1 = 0.f, a2 = 0.f, a3 = 0.f;
#pragma unroll 4
        for (int d = 0; d < HD; d += 4) {
            float u0 = U[(d + 0) * HE + tid];
            float u1 = U[(d + 1) * HE + tid];
            float u2 = U[(d + 2) * HE + tid];
            float u3 = U[(d + 3) * HE + tid];
#pragma unroll
            for (int j = 0; j < 4; j++) {
                float uj = (j == 0) ? u0 : (j == 1) ? u1 : (j == 2) ? u2 : u3;
                a0 = fmaf(sbuf[0 * HD + d + j], uj, a0);
                a1 = fmaf(sbuf[1 * HD + d + j], uj, a1);
                a2 = fmaf(sbuf[2 * HD + d + j], uj, a2);
                a3 = fmaf(sbuf[3 * HD + d + j], uj, a3);
            }
        }
        size_t base = ((size_t)(b * TD + t0)) * HE + tid;
        g_Uh[base + 0 * HE] = a0;
        g_Uh[base + 1 * HE] = a1;
        g_Uh[base + 2 * HE] = a2;
        g_Uh[base + 3 * HE] = a3;
    } else {
        // ---- Ws: rows = B*TE, 8 per block ----
        int blk = blockIdx.x - 256;
        int b  = blk >> 6;
        int s0 = (blk & 63) * 8;
        const float4* erow = reinterpret_cast<const float4*>(enc + ((size_t)b * TE + s0) * HE);
        float4* sb4 = reinterpret_cast<float4*>(sbuf);
#pragma unroll
        for (int i = 0; i < 2; i++) sb4[tid + 128 * i] = erow[tid + 128 * i];
        __syncthreads();

        float acc[8];
#pragma unroll
        for (int r = 0; r < 8; r++) acc[r] = 0.f;
#pragma unroll 2
        for (int k = 0; k < HE; k += 4) {
            float w0 = W[(k + 0) * HE + tid];
            float w1 = W[(k + 1) * HE + tid];
            float w2 = W[(k + 2) * HE + tid];
            float w3 = W[(k + 3) * HE + tid];
#pragma unroll
            for (int r = 0; r < 8; r++) {
                float aa = acc[r];
                aa = fmaf(sbuf[r * HE + k + 0], w0, aa);
                aa = fmaf(sbuf[r * HE + k + 1], w1, aa);
                aa = fmaf(sbuf[r * HE + k + 2], w2, aa);
                aa = fmaf(sbuf[r * HE + k + 3], w3, aa);
                acc[r] = aa;
            }
        }
        size_t base = ((size_t)(b * TE + s0)) * HE + tid;
#pragma unroll
        for (int r = 0; r < 8; r++) g_Ws[base + (size_t)r * HE] = acc[r];
    }
}

// ================= Fused score / softmax / context kernel =================
// One CTA per (b, tile of TT=4 decoder steps). 256 threads.
#define TT 4
#define SCH 64                         // encoder rows per smem chunk
#define WPAD 33                        // float4 row stride (132 floats, conflict-free)

__global__ __launch_bounds__(256) void score_ctx_kernel(
    const float* __restrict__ enc,
    const float* __restrict__ Va,
    float* __restrict__ c_out,   // [B,TD,HE]
    float* __restrict__ e_out)   // [B,TD,TE]
{
    __shared__ float4 s_ws[SCH * WPAD];          // 33.8 KB
    __shared__ float  s_uh[TT * HE];             // 2 KB
    __shared__ float  s_v[HE];                   // 0.5 KB
    __shared__ float  s_scores[TT * TE];         // 8 KB
    __shared__ float  s_ctx[TT * HE];            // 2 KB

    int blk = blockIdx.x;
    int b  = blk / (TD / TT);
    int t0 = (blk % (TD / TT)) * TT;
    int tid  = threadIdx.x;
    int warp = tid >> 5;
    int lane = tid & 31;

    // stage Uh tile + V
    for (int i = tid; i < TT * HE; i += 256)
        s_uh[i] = g_Uh[((size_t)(b * TD + t0)) * HE + i];
    if (tid < HE) s_v[tid] = Va[tid];
    __syncthreads();

    const float4* s_uh4 = reinterpret_cast<const float4*>(s_uh);
    const float4* s_v4  = reinterpret_cast<const float4*>(s_v);

    // ---- Phase 1: scores, thread = one (s, tt) pair per chunk ----
    int sl = tid & (SCH - 1);
    int tt = tid >> 6;                            // 256 threads / 64 = 4
    const float4* wsrc = reinterpret_cast<const float4*>(g_Ws + (size_t)b * TE * HE);

    for (int c = 0; c < TE / SCH; c++) {
        // load chunk: 64 rows x 32 float4, coalesced
        const float4* src = wsrc + (size_t)c * SCH * (HE / 4);
        for (int i = tid; i < SCH * (HE / 4); i += 256) {
            int r = i >> 5, q = i & 31;
            s_ws[r * WPAD + q] = src[r * 32 + q];
        }
        __syncthreads();

        const float4* wrow = s_ws + sl * WPAD;
        const float4* urow = s_uh4 + tt * (HE / 4);
        float acc = 0.f;
#pragma unroll 8
        for (int q = 0; q < HE / 4; q++) {
            float4 w = wrow[q];
            float4 u = urow[q];
            float4 v = s_v4[q];
            acc = fmaf(fast_tanh(w.x + u.x), v.x, acc);
            acc = fmaf(fast_tanh(w.y + u.y), v.y, acc);
            acc = fmaf(fast_tanh(w.z + u.z), v.z, acc);
            acc = fmaf(fast_tanh(w.w + u.w), v.w, acc);
        }
        s_scores[tt * TE + c * SCH + sl] = acc;
        __syncthreads();
    }

    // ---- Phase 2: softmax per decoder step (warps 0..3) ----
    if (warp < TT) {
        int t = warp;
        float* sc = s_scores + t * TE;
        float m = -1e30f;
        for (int s = lane; s < TE; s += 32) m = fmaxf(m, sc[s]);
#pragma unroll
        for (int o = 16; o > 0; o >>= 1)
            m = fmaxf(m, __shfl_xor_sync(0xFFFFFFFFu, m, o));
        float sum = 0.f;
        for (int s = lane; s < TE; s += 32) {
            float ex = __expf(sc[s] - m);
            sc[s] = ex;
            sum += ex;
        }
#pragma unroll
        for (int o = 16; o > 0; o >>= 1)
            sum += __shfl_xor_sync(0xFFFFFFFFu, sum, o);
        float inv = 1.0f / sum;
        float* eo = e_out + ((size_t)(b * TD + t0 + t)) * TE;
        for (int s = lane; s < TE; s += 32) {
            float w = sc[s] * inv;
            sc[s] = w;
            eo[s] = w;
        }
    }
    __syncthreads();

    // ---- Phase 3: context, s unrolled by 4 with float4 score broadcasts ----
    int g  = tid >> 7;                  // 0 or 1: split s range
    int ee = tid & 127;                 // output feature
    const float* encb = enc + (size_t)b * TE * HE;
    float a0 = 0.f, a1 = 0.f, a2 = 0.f, a3 = 0.f;
    int sbeg = g * (TE / 2);
#pragma unroll 2
    for (int s = sbeg; s < sbeg + TE / 2; s += 4) {
        float4 w0 = *reinterpret_cast<const float4*>(&s_scores[0 * TE + s]);
        float4 w1 = *reinterpret_cast<const float4*>(&s_scores[1 * TE + s]);
        float4 w2 = *reinterpret_cast<const float4*>(&s_scores[2 * TE + s]);
        float4 w3 = *reinterpret_cast<const float4*>(&s_scores[3 * TE + s]);
        float x0 = encb[(size_t)(s + 0) * HE + ee];
        float x1 = encb[(size_t)(s + 1) * HE + ee];
        float x2 = encb[(size_t)(s + 2) * HE + ee];
        float x3 = encb[(size_t)(s + 3) * HE + ee];
        a0 = fmaf(w0.x, x0, fmaf(w0.y, x1, fmaf(w0.z, x2, fmaf(w0.w, x3, a0))));
        a1 = fmaf(w1.x, x0, fmaf(w1.y, x1, fmaf(w1.z, x2, fmaf(w1.w, x3, a1))));
        a2 = fmaf(w2.x, x0, fmaf(w2.y, x1, fmaf(w2.z, x2, fmaf(w2.w, x3, a2))));
        a3 = fmaf(w3.x, x0, fmaf(w3.y, x1, fmaf(w3.z, x2, fmaf(w3.w, x3, a3))));
    }
    if (g == 1) {
        s_ctx[0 * HE + ee] = a0;
        s_ctx[1 * HE + ee] = a1;
        s_ctx[2 * HE + ee] = a2;
        s_ctx[3 * HE + ee] = a3;
    }
    __syncthreads();
    if (g == 0) {
        a0 += s_ctx[0 * HE + ee];
        a1 += s_ctx[1 * HE + ee];
        a2 += s_ctx[2 * HE + ee];
        a3 += s_ctx[3 * HE + ee];
        size_t base = ((size_t)(b * TD + t0)) * HE + ee;
        c_out[base + 0 * HE] = a0;
        c_out[base + 1 * HE] = a1;
        c_out[base + 2 * HE] = a2;
        c_out[base + 3 * HE] = a3;
    }
}

extern "C" void kernel_launch(void* const* d_in, const int* in_sizes, int n_in,
                              void* d_out, int out_size) {
    const float* enc = (const float*)d_in[0];   // [B,TE,HE]
    const float* dec = (const float*)d_in[1];   // [B,TD,HD]
    const float* Wa  = (const float*)d_in[2];   // [HE,HE]
    const float* Ua  = (const float*)d_in[3];   // [HD,HE]
    const float* Va  = (const float*)d_in[4];   // [HE,1]

    float* out   = (float*)d_out;
    float* c_out = out;                          // [B,TD,HE]
    float* e_out = out + (size_t)BB * TD * HE;   // [B,TD,TE]

    prep_kernel<<<512, 128>>>(dec, Ua, enc, Wa);
    score_ctx_kernel<<<BB * (TD / TT), 256>>>(enc, Va, c_out, e_out);
}

// round 4
// speedup vs baseline: 1.7315x; 1.0367x over previous
#include <cuda_runtime.h>
#include <cuda_bf16.h>
#include <cstdint>

#define BB 4
#define TE 512
#define TD 256
#define HE 128
#define HD 256

// ---- scratch (device globals; no allocation allowed) ----
__device__ float g_Ws[BB * TE * HE];   // enc @ W_a   [B,TE,HE]  (1 MB)
__device__ float g_Uh[BB * TD * HE];   // dec @ U_a   [B,TD,HE]  (0.5 MB)

__device__ __forceinline__ float fast_tanh(float x) {
    float y;
    asm("tanh.approx.f32 %0, %1;" : "=f"(y) : "f"(x));
    return y;
}

// ================= Prep kernel: Uh = dec@U  and  Ws = enc@W =================
__global__ __launch_bounds__(128) void prep_kernel(
    const float* __restrict__ dec, const float* __restrict__ U,
    const float* __restrict__ enc, const float* __restrict__ W)
{
    __shared__ float sbuf[1024];                 // 4 KB
    int tid = threadIdx.x;

    if (blockIdx.x < 256) {
        // ---- Uh: rows = B*TD, 4 per block ----
        int blk = blockIdx.x;
        int b  = blk >> 6;
        int t0 = (blk & 63) * 4;
        const float4* drow = reinterpret_cast<const float4*>(dec + ((size_t)b * TD + t0) * HD);
        float4* sb4 = reinterpret_cast<float4*>(sbuf);
#pragma unroll
        for (int i = 0; i < 2; i++) sb4[tid + 128 * i] = drow[tid + 128 * i];
        __syncthreads();

        float a0 = 0.f, a1 = 0.f, a2 = 0.f, a3 = 0.f;
#pragma unroll 4
        for (int d = 0; d < HD; d += 4) {
            float u0 = U[(d + 0) * HE + tid];
            float u1 = U[(d + 1) * HE + tid];
            float u2 = U[(d + 2) * HE + tid];
            float u3 = U[(d + 3) * HE + tid];
#pragma unroll
            for (int j = 0; j < 4; j++) {
                float uj = (j == 0) ? u0 : (j == 1) ? u1 : (j == 2) ? u2 : u3;
                a0 = fmaf(sbuf[0 * HD + d + j], uj, a0);
                a1 = fmaf(sbuf[1 * HD + d + j], uj, a1);
                a2 = fmaf(sbuf[2 * HD + d + j], uj, a2);
                a3 = fmaf(sbuf[3 * HD + d + j], uj, a3);
            }
        }
        size_t base = ((size_t)(b * TD + t0)) * HE + tid;
        g_Uh[base + 0 * HE] = a0;
        g_Uh[base + 1 * HE] = a1;
        g_Uh[base + 2 * HE] = a2;
        g_Uh[base + 3 * HE] = a3;
    } else {
        // ---- Ws: rows = B*TE, 8 per block ----
        int blk = blockIdx.x - 256;
        int b  = blk >> 6;
        int s0 = (blk & 63) * 8;
        const float4* erow = reinterpret_cast<const float4*>(enc + ((size_t)b * TE + s0) * HE);
        float4* sb4 = reinterpret_cast<float4*>(sbuf);
#pragma unroll
        for (int i = 0; i < 2; i++) sb4[tid + 128 * i] = erow[tid + 128 * i];
        __syncthreads();

        float acc[8];
#pragma unroll
        for (int r = 0; r < 8; r++) acc[r] = 0.f;
#pragma unroll 2
        for (int k = 0; k < HE; k += 4) {
            float w0 = W[(k + 0) * HE + tid];
            float w1 = W[(k + 1) * HE + tid];
            float w2 = W[(k + 2) * HE + tid];
            float w3 = W[(k + 3) * HE + tid];
#pragma unroll
            for (int r = 0; r < 8; r++) {
                float aa = acc[r];
                aa = fmaf(sbuf[r * HE + k + 0], w0, aa);
                aa = fmaf(sbuf[r * HE + k + 1], w1, aa);
                aa = fmaf(sbuf[r * HE + k + 2], w2, aa);
                aa = fmaf(sbuf[r * HE + k + 3], w3, aa);
                acc[r] = aa;
            }
        }
        size_t base = ((size_t)(b * TE + s0)) * HE + tid;
#pragma unroll
        for (int r = 0; r < 8; r++) g_Ws[base + (size_t)r * HE] = acc[r];
    }
}

// ================= Fused score / softmax / context kernel =================
// One CTA per (b, tile of TT=4 decoder steps). 512 threads = 16 warps.
// Each thread owns exactly one encoder position s = tid, accumulating all
// TT scores in registers; Ws is read straight from L2 (no smem staging).
#define TT 4
__global__ __launch_bounds__(512) void score_ctx_kernel(
    const float* __restrict__ enc,
    const float* __restrict__ Va,
    float* __restrict__ c_out,   // [B,TD,HE]
    float* __restrict__ e_out)   // [B,TD,TE]
{
    __shared__ float s_uh[TT * HE];              // 2 KB
    __shared__ float s_v[HE];                    // 0.5 KB
    __shared__ float s_scores[TT * TE];          // 8 KB
    __shared__ float s_ctx[4][TT * HE];          // 8 KB

    int blk = blockIdx.x;
    int b  = blk / (TD / TT);
    int t0 = (blk % (TD / TT)) * TT;
    int tid  = threadIdx.x;                      // 0..511 == encoder position s
    int warp = tid >> 5;
    int lane = tid & 31;

    // stage Uh tile + V   (BUG FIX: independent predicates — with 512 threads
    // the old else-branch was dead and s_v was never initialized)
    if (tid < TT * HE)
        s_uh[tid] = g_Uh[((size_t)(b * TD + t0)) * HE + tid];
    if (tid < HE)
        s_v[tid] = Va[tid];
    __syncthreads();

    const float4* s_uh4 = reinterpret_cast<const float4*>(s_uh);
    const float4* s_v4  = reinterpret_cast<const float4*>(s_v);

    // ---- Phase 1: scores. acc over TT in registers, Ws via LDG (L2). ----
    {
        const float4* wrow = reinterpret_cast<const float4*>(
            g_Ws + ((size_t)b * TE + tid) * HE);
        float a0 = 0.f, a1 = 0.f, a2 = 0.f, a3 = 0.f;
#pragma unroll 8
        for (int q = 0; q < HE / 4; q++) {
            float4 w = wrow[q];
            float4 v = s_v4[q];
            float4 u;
            u = s_uh4[0 * (HE / 4) + q];
            a0 = fmaf(fast_tanh(w.x + u.x), v.x, a0);
            a0 = fmaf(fast_tanh(w.y + u.y), v.y, a0);
            a0 = fmaf(fast_tanh(w.z + u.z), v.z, a0);
            a0 = fmaf(fast_tanh(w.w + u.w), v.w, a0);
            u = s_uh4[1 * (HE / 4) + q];
            a1 = fmaf(fast_tanh(w.x + u.x), v.x, a1);
            a1 = fmaf(fast_tanh(w.y + u.y), v.y, a1);
            a1 = fmaf(fast_tanh(w.z + u.z), v.z, a1);
            a1 = fmaf(fast_tanh(w.w + u.w), v.w, a1);
            u = s_uh4[2 * (HE / 4) + q];
            a2 = fmaf(fast_tanh(w.x + u.x), v.x, a2);
            a2 = fmaf(fast_tanh(w.y + u.y), v.y, a2);
            a2 = fmaf(fast_tanh(w.z + u.z), v.z, a2);
            a2 = fmaf(fast_tanh(w.w + u.w), v.w, a2);
            u = s_uh4[3 * (HE / 4) + q];
            a3 = fmaf(fast_tanh(w.x + u.x), v.x, a3);
            a3 = fmaf(fast_tanh(w.y + u.y), v.y, a3);
            a3 = fmaf(fast_tanh(w.z + u.z), v.z, a3);
            a3 = fmaf(fast_tanh(w.w + u.w), v.w, a3);
        }
        s_scores[0 * TE + tid] = a0;
        s_scores[1 * TE + tid] = a1;
        s_scores[2 * TE + tid] = a2;
        s_scores[3 * TE + tid] = a3;
    }
    __syncthreads();

    // ---- Phase 2: softmax per decoder step (warps 0..3) ----
    if (warp < TT) {
        int t = warp;
        float* sc = s_scores + t * TE;
        float m = -1e30f;
        for (int s = lane; s < TE; s += 32) m = fmaxf(m, sc[s]);
#pragma unroll
        for (int o = 16; o > 0; o >>= 1)
            m = fmaxf(m, __shfl_xor_sync(0xFFFFFFFFu, m, o));
        float sum = 0.f;
        for (int s = lane; s < TE; s += 32) {
            float ex = __expf(sc[s] - m);
            sc[s] = ex;
            sum += ex;
        }
#pragma unroll
        for (int o = 16; o > 0; o >>= 1)
            sum += __shfl_xor_sync(0xFFFFFFFFu, sum, o);
        float inv = 1.0f / sum;
        float* eo = e_out + ((size_t)(b * TD + t0 + t)) * TE;
        for (int s = lane; s < TE; s += 32) {
            float w = sc[s] * inv;
            sc[s] = w;
            eo[s] = w;
        }
    }
    __syncthreads();

    // ---- Phase 3: context. 4 groups of 128 threads split the s-range. ----
    {
        int g  = tid >> 7;              // 0..3
        int ee = tid & 127;             // output feature
        const float* encb = enc + (size_t)b * TE * HE;
        float a0 = 0.f, a1 = 0.f, a2 = 0.f, a3 = 0.f;
        int sbeg = g * (TE / 4);
#pragma unroll 2
        for (int s = sbeg; s < sbeg + TE / 4; s += 4) {
            float4 w0 = *reinterpret_cast<const float4*>(&s_scores[0 * TE + s]);
            float4 w1 = *reinterpret_cast<const float4*>(&s_scores[1 * TE + s]);
            float4 w2 = *reinterpret_cast<const float4*>(&s_scores[2 * TE + s]);
            float4 w3 = *reinterpret_cast<const float4*>(&s_scores[3 * TE + s]);
            float x0 = encb[(size_t)(s + 0) * HE + ee];
            float x1 = encb[(size_t)(s + 1) * HE + ee];
            float x2 = encb[(size_t)(s + 2) * HE + ee];
            float x3 = encb[(size_t)(s + 3) * HE + ee];
            a0 = fmaf(w0.x, x0, fmaf(w0.y, x1, fmaf(w0.z, x2, fmaf(w0.w, x3, a0))));
            a1 = fmaf(w1.x, x0, fmaf(w1.y, x1, fmaf(w1.z, x2, fmaf(w1.w, x3, a1))));
            a2 = fmaf(w2.x, x0, fmaf(w2.y, x1, fmaf(w2.z, x2, fmaf(w2.w, x3, a2))));
            a3 = fmaf(w3.x, x0, fmaf(w3.y, x1, fmaf(w3.z, x2, fmaf(w3.w, x3, a3))));
        }
        s_ctx[g][0 * HE + ee] = a0;
        s_ctx[g][1 * HE + ee] = a1;
        s_ctx[g][2 * HE + ee] = a2;
        s_ctx[g][3 * HE + ee] = a3;
    }
    __syncthreads();

    // combine the 4 partial groups: 512 threads -> 512 outputs (TT*HE)
    {
        float r = s_ctx[0][tid] + s_ctx[1][tid] + s_ctx[2][tid] + s_ctx[3][tid];
        int tt = tid >> 7;              // tid / HE
        int ee = tid & 127;
        c_out[((size_t)(b * TD + t0 + tt)) * HE + ee] = r;
    }
}

extern "C" void kernel_launch(void* const* d_in, const int* in_sizes, int n_in,
                              void* d_out, int out_size) {
    const float* enc = (const float*)d_in[0];   // [B,TE,HE]
    const float* dec = (const float*)d_in[1];   // [B,TD,HD]
    const float* Wa  = (const float*)d_in[2];   // [HE,HE]
    const float* Ua  = (const float*)d_in[3];   // [HD,HE]
    const float* Va  = (const float*)d_in[4];   // [HE,1]

    float* out   = (float*)d_out;
    float* c_out = out;                          // [B,TD,HE]
    float* e_out = out + (size_t)BB * TD * HE;   // [B,TD,TE]

    prep_kernel<<<512, 128>>>(dec, Ua, enc, Wa);
    score_ctx_kernel<<<BB * (TD / TT), 512>>>(enc, Va, c_out, e_out);
}

// round 5
// speedup vs baseline: 1.8101x; 1.0454x over previous
#include <cuda_runtime.h>
#include <cuda_bf16.h>
#include <cstdint>

#define BB 4
#define TE 512
#define TD 256
#define HE 128
#define HD 256

// ---- scratch (device globals; no allocation allowed) ----
__device__ float g_Ws[BB * TE * HE];   // enc @ W_a   [B,TE,HE]  (1 MB)
__device__ float g_Uh[BB * TD * HE];   // dec @ U_a   [B,TD,HE]  (0.5 MB)

__device__ __forceinline__ float fast_tanh(float x) {
    float y;
    asm("tanh.approx.f32 %0, %1;" : "=f"(y) : "f"(x));
    return y;
}

// ================= Prep kernel: Uh = dec@U  and  Ws = enc@W =================
__global__ __launch_bounds__(128) void prep_kernel(
    const float* __restrict__ dec, const float* __restrict__ U,
    const float* __restrict__ enc, const float* __restrict__ W)
{
    __shared__ float sbuf[1024];                 // 4 KB
    int tid = threadIdx.x;

    if (blockIdx.x < 256) {
        // ---- Uh: rows = B*TD, 4 per block ----
        int blk = blockIdx.x;
        int b  = blk >> 6;
        int t0 = (blk & 63) * 4;
        const float4* drow = reinterpret_cast<const float4*>(dec + ((size_t)b * TD + t0) * HD);
        float4* sb4 = reinterpret_cast<float4*>(sbuf);
#pragma unroll
        for (int i = 0; i < 2; i++) sb4[tid + 128 * i] = drow[tid + 128 * i];
        __syncthreads();

        float a0 = 0.f, a1 = 0.f, a2 = 0.f, a3 = 0.f;
#pragma unroll 4
        for (int d = 0; d < HD; d += 4) {
            float u0 = U[(d + 0) * HE + tid];
            float u1 = U[(d + 1) * HE + tid];
            float u2 = U[(d + 2) * HE + tid];
            float u3 = U[(d + 3) * HE + tid];
#pragma unroll
            for (int j = 0; j < 4; j++) {
                float uj = (j == 0) ? u0 : (j == 1) ? u1 : (j == 2) ? u2 : u3;
                a0 = fmaf(sbuf[0 * HD + d + j], uj, a0);
                a1 = fmaf(sbuf[1 * HD + d + j], uj, a1);
                a2 = fmaf(sbuf[2 * HD + d + j], uj, a2);
                a3 = fmaf(sbuf[3 * HD + d + j], uj, a3);
            }
        }
        size_t base = ((size_t)(b * TD + t0)) * HE + tid;
        g_Uh[base + 0 * HE] = a0;
        g_Uh[base + 1 * HE] = a1;
        g_Uh[base + 2 * HE] = a2;
        g_Uh[base + 3 * HE] = a3;
    } else {
        // ---- Ws: rows = B*TE, 8 per block ----
        int blk = blockIdx.x - 256;
        int b  = blk >> 6;
        int s0 = (blk & 63) * 8;
        const float4* erow = reinterpret_cast<const float4*>(enc + ((size_t)b * TE + s0) * HE);
        float4* sb4 = reinterpret_cast<float4*>(sbuf);
#pragma unroll
        for (int i = 0; i < 2; i++) sb4[tid + 128 * i] = erow[tid + 128 * i];
        __syncthreads();

        float acc[8];
#pragma unroll
        for (int r = 0; r < 8; r++) acc[r] = 0.f;
#pragma unroll 2
        for (int k = 0; k < HE; k += 4) {
            float w0 = W[(k + 0) * HE + tid];
            float w1 = W[(k + 1) * HE + tid];
            float w2 = W[(k + 2) * HE + tid];
            float w3 = W[(k + 3) * HE + tid];
#pragma unroll
            for (int r = 0; r < 8; r++) {
                float aa = acc[r];
                aa = fmaf(sbuf[r * HE + k + 0], w0, aa);
                aa = fmaf(sbuf[r * HE + k + 1], w1, aa);
                aa = fmaf(sbuf[r * HE + k + 2], w2, aa);
                aa = fmaf(sbuf[r * HE + k + 3], w3, aa);
                acc[r] = aa;
            }
        }
        size_t base = ((size_t)(b * TE + s0)) * HE + tid;
#pragma unroll
        for (int r = 0; r < 8; r++) g_Ws[base + (size_t)r * HE] = acc[r];
    }
}

// ================= Fused score / softmax / context kernel =================
// One CTA per (b, tile of TT=4 decoder steps). 256 threads = 8 warps.
// Each thread owns TWO encoder positions (tid, tid+256): per q-iter the
// 5 broadcast LDS + 2 LDG feed 32 tanh evaluations (2x better than before).
#define TT 4
__global__ __launch_bounds__(256) void score_ctx_kernel(
    const float* __restrict__ enc,
    const float* __restrict__ Va,
    float* __restrict__ c_out,   // [B,TD,HE]
    float* __restrict__ e_out)   // [B,TD,TE]
{
    __shared__ float s_uh[TT * HE];              // 2 KB
    __shared__ float s_v[HE];                    // 0.5 KB
    __shared__ float s_scores[TT * TE];          // 8 KB
    __shared__ float s_ctx[TT * HE];             // 2 KB

    int blk = blockIdx.x;
    int b  = blk / (TD / TT);
    int t0 = (blk % (TD / TT)) * TT;
    int tid  = threadIdx.x;                      // 0..255
    int warp = tid >> 5;
    int lane = tid & 31;

    // stage Uh tile + V
    for (int i = tid; i < TT * HE; i += 256)
        s_uh[i] = g_Uh[((size_t)(b * TD + t0)) * HE + i];
    if (tid < HE) s_v[tid] = Va[tid];
    __syncthreads();

    const float4* s_uh4 = reinterpret_cast<const float4*>(s_uh);
    const float4* s_v4  = reinterpret_cast<const float4*>(s_v);

    // ---- Phase 1: scores for s=tid and s=tid+256, all TT steps ----
    {
        const float4* w0p = reinterpret_cast<const float4*>(
            g_Ws + ((size_t)b * TE + tid) * HE);
        const float4* w1p = w0p + 256 * (HE / 4);
        float acc0[TT], acc1[TT];
#pragma unroll
        for (int t = 0; t < TT; t++) { acc0[t] = 0.f; acc1[t] = 0.f; }

#pragma unroll 4
        for (int q = 0; q < HE / 4; q++) {
            float4 w0 = w0p[q];
            float4 w1 = w1p[q];
            float4 v  = s_v4[q];
#pragma unroll
            for (int t = 0; t < TT; t++) {
                float4 u = s_uh4[t * (HE / 4) + q];
                float a = acc0[t];
                a = fmaf(fast_tanh(w0.x + u.x), v.x, a);
                a = fmaf(fast_tanh(w0.y + u.y), v.y, a);
                a = fmaf(fast_tanh(w0.z + u.z), v.z, a);
                a = fmaf(fast_tanh(w0.w + u.w), v.w, a);
                acc0[t] = a;
                float c = acc1[t];
                c = fmaf(fast_tanh(w1.x + u.x), v.x, c);
                c = fmaf(fast_tanh(w1.y + u.y), v.y, c);
                c = fmaf(fast_tanh(w1.z + u.z), v.z, c);
                c = fmaf(fast_tanh(w1.w + u.w), v.w, c);
                acc1[t] = c;
            }
        }
#pragma unroll
        for (int t = 0; t < TT; t++) {
            s_scores[t * TE + tid]       = acc0[t];
            s_scores[t * TE + tid + 256] = acc1[t];
        }
    }
    __syncthreads();

    // ---- Phase 2: softmax per decoder step (warps 0..3) ----
    if (warp < TT) {
        int t = warp;
        float* sc = s_scores + t * TE;
        float m = -1e30f;
        for (int s = lane; s < TE; s += 32) m = fmaxf(m, sc[s]);
#pragma unroll
        for (int o = 16; o > 0; o >>= 1)
            m = fmaxf(m, __shfl_xor_sync(0xFFFFFFFFu, m, o));
        float sum = 0.f;
        for (int s = lane; s < TE; s += 32) {
            float ex = __expf(sc[s] - m);
            sc[s] = ex;
            sum += ex;
        }
#pragma unroll
        for (int o = 16; o > 0; o >>= 1)
            sum += __shfl_xor_sync(0xFFFFFFFFu, sum, o);
        float inv = 1.0f / sum;
        float* eo = e_out + ((size_t)(b * TD + t0 + t)) * TE;
        for (int s = lane; s < TE; s += 32) {
            float w = sc[s] * inv;
            sc[s] = w;
            eo[s] = w;
        }
    }
    __syncthreads();

    // ---- Phase 3: context. 2 groups of 128 threads split the s-range. ----
    {
        int g  = tid >> 7;              // 0 or 1
        int ee = tid & 127;             // output feature
        const float* encb = enc + (size_t)b * TE * HE;
        float a0 = 0.f, a1 = 0.f, a2 = 0.f, a3 = 0.f;
        int sbeg = g * (TE / 2);
#pragma unroll 2
        for (int s = sbeg; s < sbeg + TE / 2; s += 4) {
            float4 w0 = *reinterpret_cast<const float4*>(&s_scores[0 * TE + s]);
            float4 w1 = *reinterpret_cast<const float4*>(&s_scores[1 * TE + s]);
            float4 w2 = *reinterpret_cast<const float4*>(&s_scores[2 * TE + s]);
            float4 w3 = *reinterpret_cast<const float4*>(&s_scores[3 * TE + s]);
            float x0 = encb[(size_t)(s + 0) * HE + ee];
            float x1 = encb[(size_t)(s + 1) * HE + ee];
            float x2 = encb[(size_t)(s + 2) * HE + ee];
            float x3 = encb[(size_t)(s + 3) * HE + ee];
            a0 = fmaf(w0.x, x0, fmaf(w0.y, x1, fmaf(w0.z, x2, fmaf(w0.w, x3, a0))));
            a1 = fmaf(w1.x, x0, fmaf(w1.y, x1, fmaf(w1.z, x2, fmaf(w1.w, x3, a1))));
            a2 = fmaf(w2.x, x0, fmaf(w2.y, x1, fmaf(w2.z, x2, fmaf(w2.w, x3, a2))));
            a3 = fmaf(w3.x, x0, fmaf(w3.y, x1, fmaf(w3.z, x2, fmaf(w3.w, x3, a3))));
        }
        if (g == 1) {
            s_ctx[0 * HE + ee] = a0;
            s_ctx[1 * HE + ee] = a1;
            s_ctx[2 * HE + ee] = a2;
            s_ctx[3 * HE + ee] = a3;
        }
        __syncthreads();
        if (g == 0) {
            a0 += s_ctx[0 * HE + ee];
            a1 += s_ctx[1 * HE + ee];
            a2 += s_ctx[2 * HE + ee];
            a3 += s_ctx[3 * HE + ee];
            size_t base = ((size_t)(b * TD + t0)) * HE + ee;
            c_out[base + 0 * HE] = a0;
            c_out[base + 1 * HE] = a1;
            c_out[base + 2 * HE] = a2;
            c_out[base + 3 * HE] = a3;
        }
    }
}

extern "C" void kernel_launch(void* const* d_in, const int* in_sizes, int n_in,
                              void* d_out, int out_size) {
    const float* enc = (const float*)d_in[0];   // [B,TE,HE]
    const float* dec = (const float*)d_in[1];   // [B,TD,HD]
    const float* Wa  = (const float*)d_in[2];   // [HE,HE]
    const float* Ua  = (const float*)d_in[3];   // [HD,HE]
    const float* Va  = (const float*)d_in[4];   // [HE,1]

    float* out   = (float*)d_out;
    float* c_out = out;                          // [B,TD,HE]
    float* e_out = out + (size_t)BB * TD * HE;   // [B,TD,TE]

    prep_kernel<<<512, 128>>>(dec, Ua, enc, Wa);
    score_ctx_kernel<<<BB * (TD / TT), 256>>>(enc, Va, c_out, e_out);
}

// round 6
// speedup vs baseline: 1.8215x; 1.0063x over previous
#include <cuda_runtime.h>
#include <cuda_bf16.h>
#include <cstdint>

#define BB 4
#define TE 512
#define TD 256
#define HE 128
#define HD 256
#define TT 4

// ---- scratch (device globals; no allocation allowed) ----
__device__ float g_Ws[BB * TE * HE];        // enc @ W_a   [B,TE,HE]  (1 MB)
__device__ float g_Uh[BB * TD * HE];        // dec @ U_a   [B,TD,HE]  (0.5 MB)
__device__ float g_scores[BB * TD * TE];    // raw scores  [B,TD,TE]  (2 MB)

__device__ __forceinline__ float fast_tanh(float x) {
    float y;
    asm("tanh.approx.f32 %0, %1;" : "=f"(y) : "f"(x));
    return y;
}

// ================= Prep kernel: Uh = dec@U  and  Ws = enc@W =================
__global__ __launch_bounds__(128) void prep_kernel(
    const float* __restrict__ dec, const float* __restrict__ U,
    const float* __restrict__ enc, const float* __restrict__ W)
{
    __shared__ float sbuf[1024];                 // 4 KB
    int tid = threadIdx.x;

    if (blockIdx.x < 256) {
        // ---- Uh: rows = B*TD, 4 per block ----
        int blk = blockIdx.x;
        int b  = blk >> 6;
        int t0 = (blk & 63) * 4;
        const float4* drow = reinterpret_cast<const float4*>(dec + ((size_t)b * TD + t0) * HD);
        float4* sb4 = reinterpret_cast<float4*>(sbuf);
#pragma unroll
        for (int i = 0; i < 2; i++) sb4[tid + 128 * i] = drow[tid + 128 * i];
        __syncthreads();

        float a0 = 0.f, a1 = 0.f, a2 = 0.f, a3 = 0.f;
#pragma unroll 4
        for (int d = 0; d < HD; d += 4) {
            float u0 = U[(d + 0) * HE + tid];
            float u1 = U[(d + 1) * HE + tid];
            float u2 = U[(d + 2) * HE + tid];
            float u3 = U[(d + 3) * HE + tid];
#pragma unroll
            for (int j = 0; j < 4; j++) {
                float uj = (j == 0) ? u0 : (j == 1) ? u1 : (j == 2) ? u2 : u3;
                a0 = fmaf(sbuf[0 * HD + d + j], uj, a0);
                a1 = fmaf(sbuf[1 * HD + d + j], uj, a1);
                a2 = fmaf(sbuf[2 * HD + d + j], uj, a2);
                a3 = fmaf(sbuf[3 * HD + d + j], uj, a3);
            }
        }
        size_t base = ((size_t)(b * TD + t0)) * HE + tid;
        g_Uh[base + 0 * HE] = a0;
        g_Uh[base + 1 * HE] = a1;
        g_Uh[base + 2 * HE] = a2;
        g_Uh[base + 3 * HE] = a3;
    } else {
        // ---- Ws: rows = B*TE, 8 per block ----
        int blk = blockIdx.x - 256;
        int b  = blk >> 6;
        int s0 = (blk & 63) * 8;
        const float4* erow = reinterpret_cast<const float4*>(enc + ((size_t)b * TE + s0) * HE);
        float4* sb4 = reinterpret_cast<float4*>(sbuf);
#pragma unroll
        for (int i = 0; i < 2; i++) sb4[tid + 128 * i] = erow[tid + 128 * i];
        __syncthreads();

        float acc[8];
#pragma unroll
        for (int r = 0; r < 8; r++) acc[r] = 0.f;
#pragma unroll 2
        for (int k = 0; k < HE; k += 4) {
            float w0 = W[(k + 0) * HE + tid];
            float w1 = W[(k + 1) * HE + tid];
            float w2 = W[(k + 2) * HE + tid];
            float w3 = W[(k + 3) * HE + tid];
#pragma unroll
            for (int r = 0; r < 8; r++) {
                float aa = acc[r];
                aa = fmaf(sbuf[r * HE + k + 0], w0, aa);
                aa = fmaf(sbuf[r * HE + k + 1], w1, aa);
                aa = fmaf(sbuf[r * HE + k + 2], w2, aa);
                aa = fmaf(sbuf[r * HE + k + 3], w3, aa);
                acc[r] = aa;
            }
        }
        size_t base = ((size_t)(b * TE + s0)) * HE + tid;
#pragma unroll
        for (int r = 0; r < 8; r++) g_Ws[base + (size_t)r * HE] = acc[r];
    }
}

// ================= Score kernel =================
// 1024 CTAs: blk = ((b*4 + chunk)*64 + ttile)   -> 64 consecutive CTAs share
// the same 128-row Ws chunk (L2 locality). 128 threads, thread = one s.
__global__ __launch_bounds__(128) void score_kernel(const float* __restrict__ Va)
{
    __shared__ float s_uh[TT * HE];              // 2 KB
    __shared__ float s_v[HE];                    // 0.5 KB

    int blk   = blockIdx.x;
    int ttile = blk & 63;
    int chunk = (blk >> 6) & 3;
    int b     = blk >> 8;
    int t0    = ttile * TT;
    int tid   = threadIdx.x;                     // 0..127
    int s     = chunk * 128 + tid;

    // stage Uh tile + V
#pragma unroll
    for (int i = 0; i < TT; i++)
        s_uh[i * HE + tid] = g_Uh[((size_t)(b * TD + t0 + i)) * HE + tid];
    s_v[tid] = Va[tid];
    __syncthreads();

    const float4* s_uh4 = reinterpret_cast<const float4*>(s_uh);
    const float4* s_v4  = reinterpret_cast<const float4*>(s_v);
    const float4* wrow  = reinterpret_cast<const float4*>(
        g_Ws + ((size_t)b * TE + s) * HE);

    float a0 = 0.f, a1 = 0.f, a2 = 0.f, a3 = 0.f;
#pragma unroll 8
    for (int q = 0; q < HE / 4; q++) {
        float4 w = wrow[q];
        float4 v = s_v4[q];
        float4 u;
        u = s_uh4[0 * (HE / 4) + q];
        a0 = fmaf(fast_tanh(w.x + u.x), v.x, a0);
        a0 = fmaf(fast_tanh(w.y + u.y), v.y, a0);
        a0 = fmaf(fast_tanh(w.z + u.z), v.z, a0);
        a0 = fmaf(fast_tanh(w.w + u.w), v.w, a0);
        u = s_uh4[1 * (HE / 4) + q];
        a1 = fmaf(fast_tanh(w.x + u.x), v.x, a1);
        a1 = fmaf(fast_tanh(w.y + u.y), v.y, a1);
        a1 = fmaf(fast_tanh(w.z + u.z), v.z, a1);
        a1 = fmaf(fast_tanh(w.w + u.w), v.w, a1);
        u = s_uh4[2 * (HE / 4) + q];
        a2 = fmaf(fast_tanh(w.x + u.x), v.x, a2);
        a2 = fmaf(fast_tanh(w.y + u.y), v.y, a2);
        a2 = fmaf(fast_tanh(w.z + u.z), v.z, a2);
        a2 = fmaf(fast_tanh(w.w + u.w), v.w, a2);
        u = s_uh4[3 * (HE / 4) + q];
        a3 = fmaf(fast_tanh(w.x + u.x), v.x, a3);
        a3 = fmaf(fast_tanh(w.y + u.y), v.y, a3);
        a3 = fmaf(fast_tanh(w.z + u.z), v.z, a3);
        a3 = fmaf(fast_tanh(w.w + u.w), v.w, a3);
    }
    size_t base = ((size_t)(b * TD + t0)) * TE + s;
    g_scores[base + 0 * TE] = a0;
    g_scores[base + 1 * TE] = a1;
    g_scores[base + 2 * TE] = a2;
    g_scores[base + 3 * TE] = a3;
}

// ================= Softmax + context kernel =================
// grid 256 = (b, t-tile of 4), 512 threads.
__global__ __launch_bounds__(512) void smctx_kernel(
    const float* __restrict__ enc,
    float* __restrict__ c_out,   // [B,TD,HE]
    float* __restrict__ e_out)   // [B,TD,TE]
{
    __shared__ float s_scores[TT * TE];          // 8 KB
    __shared__ float s_ctx[4][TT * HE];          // 8 KB

    int blk = blockIdx.x;
    int b  = blk / (TD / TT);
    int t0 = (blk % (TD / TT)) * TT;
    int tid  = threadIdx.x;                      // 0..511
    int warp = tid >> 5;
    int lane = tid & 31;

    // load raw scores (coalesced per t)
#pragma unroll
    for (int t = 0; t < TT; t++)
        s_scores[t * TE + tid] = g_scores[((size_t)(b * TD + t0 + t)) * TE + tid];
    __syncthreads();

    // ---- softmax per decoder step (warps 0..3) ----
    if (warp < TT) {
        int t = warp;
        float* sc = s_scores + t * TE;
        float m = -1e30f;
        for (int s = lane; s < TE; s += 32) m = fmaxf(m, sc[s]);
#pragma unroll
        for (int o = 16; o > 0; o >>= 1)
            m = fmaxf(m, __shfl_xor_sync(0xFFFFFFFFu, m, o));
        float sum = 0.f;
        for (int s = lane; s < TE; s += 32) {
            float ex = __expf(sc[s] - m);
            sc[s] = ex;
            sum += ex;
        }
#pragma unroll
        for (int o = 16; o > 0; o >>= 1)
            sum += __shfl_xor_sync(0xFFFFFFFFu, sum, o);
        float inv = 1.0f / sum;
        float* eo = e_out + ((size_t)(b * TD + t0 + t)) * TE;
        for (int s = lane; s < TE; s += 32) {
            float w = sc[s] * inv;
            sc[s] = w;
            eo[s] = w;
        }
    }
    __syncthreads();

    // ---- context: 4 groups of 128 threads split the s-range ----
    {
        int g  = tid >> 7;              // 0..3
        int ee = tid & 127;             // output feature
        const float* encb = enc + (size_t)b * TE * HE;
        float a0 = 0.f, a1 = 0.f, a2 = 0.f, a3 = 0.f;
        int sbeg = g * (TE / 4);
#pragma unroll 2
        for (int s = sbeg; s < sbeg + TE / 4; s += 4) {
            float4 w0 = *reinterpret_cast<const float4*>(&s_scores[0 * TE + s]);
            float4 w1 = *reinterpret_cast<const float4*>(&s_scores[1 * TE + s]);
            float4 w2 = *reinterpret_cast<const float4*>(&s_scores[2 * TE + s]);
            float4 w3 = *reinterpret_cast<const float4*>(&s_scores[3 * TE + s]);
            float x0 = encb[(size_t)(s + 0) * HE + ee];
            float x1 = encb[(size_t)(s + 1) * HE + ee];
            float x2 = encb[(size_t)(s + 2) * HE + ee];
            float x3 = encb[(size_t)(s + 3) * HE + ee];
            a0 = fmaf(w0.x, x0, fmaf(w0.y, x1, fmaf(w0.z, x2, fmaf(w0.w, x3, a0))));
            a1 = fmaf(w1.x, x0, fmaf(w1.y, x1, fmaf(w1.z, x2, fmaf(w1.w, x3, a1))));
            a2 = fmaf(w2.x, x0, fmaf(w2.y, x1, fmaf(w2.z, x2, fmaf(w2.w, x3, a2))));
            a3 = fmaf(w3.x, x0, fmaf(w3.y, x1, fmaf(w3.z, x2, fmaf(w3.w, x3, a3))));
        }
        s_ctx[g][0 * HE + ee] = a0;
        s_ctx[g][1 * HE + ee] = a1;
        s_ctx[g][2 * HE + ee] = a2;
        s_ctx[g][3 * HE + ee] = a3;
    }
    __syncthreads();

    // combine: 512 threads -> 512 outputs (TT*HE)
    {
        float r = s_ctx[0][tid] + s_ctx[1][tid] + s_ctx[2][tid] + s_ctx[3][tid];
        int tt = tid >> 7;
        int ee = tid & 127;
        c_out[((size_t)(b * TD + t0 + tt)) * HE + ee] = r;
    }
}

extern "C" void kernel_launch(void* const* d_in, const int* in_sizes, int n_in,
                              void* d_out, int out_size) {
    const float* enc = (const float*)d_in[0];   // [B,TE,HE]
    const float* dec = (const float*)d_in[1];   // [B,TD,HD]
    const float* Wa  = (const float*)d_in[2];   // [HE,HE]
    const float* Ua  = (const float*)d_in[3];   // [HD,HE]
    const float* Va  = (const float*)d_in[4];   // [HE,1]

    float* out   = (float*)d_out;
    float* c_out = out;                          // [B,TD,HE]
    float* e_out = out + (size_t)BB * TD * HE;   // [B,TD,TE]

    prep_kernel<<<512, 128>>>(dec, Ua, enc, Wa);
    score_kernel<<<BB * 4 * 64, 128>>>(Va);
    smctx_kernel<<<BB * (TD / TT), 512>>>(enc, c_out, e_out);
}